// round 2
// baseline (speedup 1.0000x reference)
#include <cuda_runtime.h>
#include <cuda_bf16.h>
#include <cstdint>

#define NROWS 8192
#define DDIM  1024

#define MT 128
#define NT 128
#define KT 32
#define KSTRIDE 40              // bf16 elems per smem row (32 + 8 pad -> 80B, 16B-multiple, conflict-free frag loads)
#define JSPLIT 2
#define JTILES_PER (NROWS / JSPLIT / NT)   // 32
#define KCHUNKS (DDIM / KT)                // 32

// Scratch (device globals — no runtime allocation allowed)
__device__ __nv_bfloat16 g_xb[(size_t)NROWS * DDIM];   // bf16 copy of x_real
__device__ float g_sq[NROWS];                          // row squared norms (fp32)
__device__ float g_cand[JSPLIT][NROWS][5];             // per-split 5 smallest d^2 per row

__device__ __forceinline__ void ins5(float t[5], float v) {
    if (v < t[4]) {
        t[4] = v;
        if (t[4] < t[3]) { float x = t[3]; t[3] = t[4]; t[4] = x;
        if (t[3] < t[2]) { float x = t[2]; t[2] = t[3]; t[3] = x;
        if (t[2] < t[1]) { float x = t[1]; t[1] = t[2]; t[2] = x;
        if (t[1] < t[0]) { float x = t[0]; t[0] = t[1]; t[1] = x; } } } }
    }
}

// ---------------------------------------------------------------------------
// Kernel A: bf16 convert + squared norms
// ---------------------------------------------------------------------------
__global__ __launch_bounds__(256) void prep_kernel(const float* __restrict__ xr) {
    int row = blockIdx.x;
    int tid = threadIdx.x;
    float4 v = reinterpret_cast<const float4*>(xr + (size_t)row * DDIM)[tid];
    __nv_bfloat162 h0 = __floats2bfloat162_rn(v.x, v.y);
    __nv_bfloat162 h1 = __floats2bfloat162_rn(v.z, v.w);
    uint2 pk;
    pk.x = *reinterpret_cast<uint32_t*>(&h0);
    pk.y = *reinterpret_cast<uint32_t*>(&h1);
    reinterpret_cast<uint2*>(g_xb + (size_t)row * DDIM)[tid] = pk;

    float s = v.x * v.x + v.y * v.y + v.z * v.z + v.w * v.w;
    #pragma unroll
    for (int o = 16; o; o >>= 1) s += __shfl_xor_sync(0xffffffffu, s, o);
    __shared__ float red[8];
    if ((tid & 31) == 0) red[tid >> 5] = s;
    __syncthreads();
    if (tid == 0) {
        float tot = 0.f;
        #pragma unroll
        for (int i = 0; i < 8; i++) tot += red[i];
        g_sq[row] = tot;
    }
}

// ---------------------------------------------------------------------------
// Kernel B: fused Gram (bf16 mma.sync) + per-row top-5 smallest d^2
// grid: (NROWS/MT, JSPLIT), 256 threads (8 warps: 4 in M x 2 in N)
// ---------------------------------------------------------------------------
__global__ __launch_bounds__(256, 1) void gram_topk_kernel() {
    // sA: [2][MT][KSTRIDE] bf16 (20480B), sB same at +20480. cand (128x41 f32 = 20992B) aliases.
    __shared__ __align__(16) unsigned char smem_raw[2 * (2 * MT * KSTRIDE * 2)];
    __nv_bfloat16 (*sA)[MT][KSTRIDE] =
        reinterpret_cast<__nv_bfloat16 (*)[MT][KSTRIDE]>(smem_raw);
    __nv_bfloat16 (*sB)[MT][KSTRIDE] =
        reinterpret_cast<__nv_bfloat16 (*)[MT][KSTRIDE]>(smem_raw + 2 * MT * KSTRIDE * 2);
    float (*cand)[41] = reinterpret_cast<float (*)[41]>(smem_raw);
    __shared__ float sqi_s[MT];
    __shared__ float sqj_s[NT];

    const int tid = threadIdx.x;
    const int wid = tid >> 5, lane = tid & 31;
    const int warp_m = wid >> 1, warp_n = wid & 1;
    const int r = lane >> 2, qq = lane & 3;
    const int i0 = blockIdx.x * MT;
    const int jb = blockIdx.y;

    if (tid < MT) sqi_s[tid] = g_sq[i0 + tid];

    float t5[4][5];
    #pragma unroll
    for (int a = 0; a < 4; a++)
        #pragma unroll
        for (int s = 0; s < 5; s++) t5[a][s] = 3.0e38f;

    __syncthreads();
    float sqi_r[4];
    #pragma unroll
    for (int a = 0; a < 4; a++) sqi_r[a] = sqi_s[warp_m * 32 + a * 8 + r];

    auto load_chunk = [&](int kc, int buf, int j0) {
        const int k0 = kc * KT;
        #pragma unroll
        for (int part = 0; part < 2; part++) {
            int id  = tid + part * 256;   // 512 uint4 per tile
            int row = id >> 2, q = id & 3;
            uint32_t sa = (uint32_t)__cvta_generic_to_shared(&sA[buf][row][q * 8]);
            const void* ga = g_xb + (size_t)(i0 + row) * DDIM + k0 + q * 8;
            asm volatile("cp.async.cg.shared.global [%0], [%1], 16;\n" :: "r"(sa), "l"(ga));
            uint32_t sb = (uint32_t)__cvta_generic_to_shared(&sB[buf][row][q * 8]);
            const void* gb = g_xb + (size_t)(j0 + row) * DDIM + k0 + q * 8;
            asm volatile("cp.async.cg.shared.global [%0], [%1], 16;\n" :: "r"(sb), "l"(gb));
        }
    };

    #pragma unroll 1
    for (int jt = 0; jt < JTILES_PER; jt++) {
        const int j0 = jb * (NROWS / JSPLIT) + jt * NT;
        __syncthreads();                         // protect sqj_s vs previous epilogue
        if (tid < NT) sqj_s[tid] = g_sq[j0 + tid];

        float acc[2][8][4];
        #pragma unroll
        for (int mb = 0; mb < 2; mb++)
            #pragma unroll
            for (int nb = 0; nb < 8; nb++)
                #pragma unroll
                for (int e = 0; e < 4; e++) acc[mb][nb][e] = 0.f;

        load_chunk(0, 0, j0);
        asm volatile("cp.async.commit_group;\n" ::: "memory");

        #pragma unroll 1
        for (int kc = 0; kc < KCHUNKS; kc++) {
            if (kc + 1 < KCHUNKS) {
                load_chunk(kc + 1, (kc + 1) & 1, j0);
                asm volatile("cp.async.commit_group;\n" ::: "memory");
                asm volatile("cp.async.wait_group 1;\n" ::: "memory");
            } else {
                asm volatile("cp.async.wait_group 0;\n" ::: "memory");
            }
            __syncthreads();
            const int buf = kc & 1;
            #pragma unroll
            for (int ks = 0; ks < 2; ks++) {
                const int kb = ks * 16 + qq * 2;
                uint32_t a[2][4];
                #pragma unroll
                for (int mb = 0; mb < 2; mb++) {
                    int br = warp_m * 32 + mb * 16 + r;
                    a[mb][0] = *reinterpret_cast<const uint32_t*>(&sA[buf][br][kb]);
                    a[mb][1] = *reinterpret_cast<const uint32_t*>(&sA[buf][br + 8][kb]);
                    a[mb][2] = *reinterpret_cast<const uint32_t*>(&sA[buf][br][kb + 8]);
                    a[mb][3] = *reinterpret_cast<const uint32_t*>(&sA[buf][br + 8][kb + 8]);
                }
                #pragma unroll
                for (int nb = 0; nb < 8; nb++) {
                    int bn = warp_n * 64 + nb * 8 + r;
                    uint32_t b0 = *reinterpret_cast<const uint32_t*>(&sB[buf][bn][kb]);
                    uint32_t b1 = *reinterpret_cast<const uint32_t*>(&sB[buf][bn][kb + 8]);
                    #pragma unroll
                    for (int mb = 0; mb < 2; mb++) {
                        asm volatile(
                            "mma.sync.aligned.m16n8k16.row.col.f32.bf16.bf16.f32 "
                            "{%0,%1,%2,%3}, {%4,%5,%6,%7}, {%8,%9}, {%0,%1,%2,%3};\n"
                            : "+f"(acc[mb][nb][0]), "+f"(acc[mb][nb][1]),
                              "+f"(acc[mb][nb][2]), "+f"(acc[mb][nb][3])
                            : "r"(a[mb][0]), "r"(a[mb][1]), "r"(a[mb][2]), "r"(a[mb][3]),
                              "r"(b0), "r"(b1));
                    }
                }
            }
            __syncthreads();
        }

        // epilogue: d^2 + top-5 update (exclude diagonal)
        #pragma unroll
        for (int mb = 0; mb < 2; mb++)
            #pragma unroll
            for (int h = 0; h < 2; h++) {
                const int rl = warp_m * 32 + mb * 16 + h * 8 + r;
                const int gi = i0 + rl;
                const float sqi = sqi_r[mb * 2 + h];
                #pragma unroll
                for (int nb = 0; nb < 8; nb++)
                    #pragma unroll
                    for (int c = 0; c < 2; c++) {
                        const int cl = warp_n * 64 + nb * 8 + qq * 2 + c;
                        const int gj = j0 + cl;
                        float d2 = sqi + sqj_s[cl] - 2.0f * acc[mb][nb][h * 2 + c];
                        d2 = fmaxf(d2, 0.0f);
                        if (gj != gi) ins5(t5[mb * 2 + h], d2);
                    }
            }
    }

    // CTA-level merge: 8 threads x 5 candidates per row -> 5 smallest per row
    __syncthreads();
    const int g = warp_n * 4 + qq;   // 0..7 within row-group
    #pragma unroll
    for (int a = 0; a < 4; a++) {
        int rl = warp_m * 32 + a * 8 + r;
        #pragma unroll
        for (int s = 0; s < 5; s++) cand[rl][g * 5 + s] = t5[a][s];
    }
    __syncthreads();
    if (tid < MT) {
        float t[5] = {3e38f, 3e38f, 3e38f, 3e38f, 3e38f};
        #pragma unroll
        for (int k = 0; k < 40; k++) ins5(t, cand[tid][k]);
        #pragma unroll
        for (int s = 0; s < 5; s++) g_cand[jb][i0 + tid][s] = t[s];
    }
}

// ---------------------------------------------------------------------------
// Kernel C: merge splits -> score -> weight -> scale real/imag into out[2,...]
// ---------------------------------------------------------------------------
__global__ __launch_bounds__(256) void finalize_kernel(const float* __restrict__ xr,
                                                       const float* __restrict__ xi,
                                                       float* __restrict__ out) {
    const int row = blockIdx.x;
    const int tid = threadIdx.x;
    __shared__ float wsh;
    if (tid == 0) {
        float t[5] = {3e38f, 3e38f, 3e38f, 3e38f, 3e38f};
        #pragma unroll
        for (int jb = 0; jb < JSPLIT; jb++)
            #pragma unroll
            for (int s = 0; s < 5; s++) ins5(t, g_cand[jb][row][s]);
        float sc = (sqrtf(t[0]) + sqrtf(t[1]) + sqrtf(t[2]) + sqrtf(t[3]) + sqrtf(t[4])) * 0.2f;
        wsh = (sc > 0.1f) ? expf(-sc * (1.0f / 32.0f)) : 0.0f;
    }
    __syncthreads();
    const float w = wsh;
    float4 a = reinterpret_cast<const float4*>(xr + (size_t)row * DDIM)[tid];
    float4 b = reinterpret_cast<const float4*>(xi + (size_t)row * DDIM)[tid];
    a.x *= w; a.y *= w; a.z *= w; a.w *= w;
    b.x *= w; b.y *= w; b.z *= w; b.w *= w;
    reinterpret_cast<float4*>(out + (size_t)row * DDIM)[tid] = a;
    reinterpret_cast<float4*>(out + ((size_t)NROWS + row) * DDIM)[tid] = b;
}

// ---------------------------------------------------------------------------
extern "C" void kernel_launch(void* const* d_in, const int* in_sizes, int n_in,
                              void* d_out, int out_size) {
    const float* xr = (const float*)d_in[0];
    const float* xi = (const float*)d_in[1];
    float* out = (float*)d_out;

    prep_kernel<<<NROWS, 256>>>(xr);
    dim3 gridB(NROWS / MT, JSPLIT);
    gram_topk_kernel<<<gridB, 256>>>();
    finalize_kernel<<<NROWS, 256>>>(xr, xi, out);
}

// round 5
// speedup vs baseline: 1.2286x; 1.2286x over previous
#include <cuda_runtime.h>
#include <cuda_bf16.h>
#include <cstdint>

#define NROWS 8192
#define DDIM  1024
#define JSPLIT 2

#define MT 128
#define NT 128
#define KT 64                       // bf16 per K chunk
#define STR 72                      // smem row stride in bf16 elems (144B; conflict-free for ldmatrix)
#define ROWB (STR * 2)              // 144 bytes
#define NSTAGE 3
#define JTILES  (NROWS / JSPLIT / NT)     // 32
#define KCHUNKS (DDIM / KT)               // 16
#define NITERS  (JTILES * KCHUNKS)        // 512

#define ASTAGE_B (MT * ROWB)              // 18432
#define STAGE_B  (2 * ASTAGE_B)           // 36864
#define SMEM_DYN (NSTAGE * STAGE_B)       // 110592

__device__ __align__(16) __nv_bfloat16 g_xb[(size_t)NROWS * DDIM];
__device__ float g_sq[NROWS];
__device__ float g_cand[JSPLIT][NROWS][5];

__device__ __forceinline__ void ins5(float t[5], float v) {
    if (v < t[4]) {
        t[4] = v;
        if (t[4] < t[3]) { float x = t[3]; t[3] = t[4]; t[4] = x;
        if (t[3] < t[2]) { float x = t[2]; t[2] = t[3]; t[3] = x;
        if (t[2] < t[1]) { float x = t[1]; t[1] = t[2]; t[2] = x;
        if (t[1] < t[0]) { float x = t[0]; t[0] = t[1]; t[1] = x; } } } }
    }
}

__device__ __forceinline__ void cp_async16(uint32_t dst, const void* src) {
    asm volatile("cp.async.cg.shared.global [%0], [%1], 16;" :: "r"(dst), "l"(src));
}
__device__ __forceinline__ void ldm4(uint32_t r[4], uint32_t addr) {
    asm volatile("ldmatrix.sync.aligned.m8n8.x4.shared.b16 {%0,%1,%2,%3}, [%4];"
                 : "=r"(r[0]), "=r"(r[1]), "=r"(r[2]), "=r"(r[3]) : "r"(addr));
}
__device__ __forceinline__ void mma16816(float c[4], const uint32_t a[4],
                                         uint32_t b0, uint32_t b1) {
    asm volatile(
        "mma.sync.aligned.m16n8k16.row.col.f32.bf16.bf16.f32 "
        "{%0,%1,%2,%3}, {%4,%5,%6,%7}, {%8,%9}, {%0,%1,%2,%3};\n"
        : "+f"(c[0]), "+f"(c[1]), "+f"(c[2]), "+f"(c[3])
        : "r"(a[0]), "r"(a[1]), "r"(a[2]), "r"(a[3]), "r"(b0), "r"(b1));
}

// ---------------------------------------------------------------------------
// Kernel A: bf16 convert + squared norms
// ---------------------------------------------------------------------------
__global__ __launch_bounds__(256) void prep_kernel(const float* __restrict__ xr) {
    int row = blockIdx.x;
    int tid = threadIdx.x;
    float4 v = reinterpret_cast<const float4*>(xr + (size_t)row * DDIM)[tid];
    __nv_bfloat162 h0 = __floats2bfloat162_rn(v.x, v.y);
    __nv_bfloat162 h1 = __floats2bfloat162_rn(v.z, v.w);
    uint2 pk;
    pk.x = *reinterpret_cast<uint32_t*>(&h0);
    pk.y = *reinterpret_cast<uint32_t*>(&h1);
    reinterpret_cast<uint2*>(g_xb + (size_t)row * DDIM)[tid] = pk;

    float s = v.x * v.x + v.y * v.y + v.z * v.z + v.w * v.w;
    #pragma unroll
    for (int o = 16; o; o >>= 1) s += __shfl_xor_sync(0xffffffffu, s, o);
    __shared__ float red[8];
    if ((tid & 31) == 0) red[tid >> 5] = s;
    __syncthreads();
    if (tid == 0) {
        float tot = 0.f;
        #pragma unroll
        for (int i = 0; i < 8; i++) tot += red[i];
        g_sq[row] = tot;
    }
}

// ---------------------------------------------------------------------------
// Kernel B: Gram via mma.sync + ldmatrix, 3-stage cp.async pipeline,
//           fused per-row top-5.  512 threads = 16 warps (4x4), warp tile 32x32.
// ---------------------------------------------------------------------------
__global__ __launch_bounds__(512, 1) void gram_kernel() {
    extern __shared__ __align__(16) unsigned char sm[];
    const uint32_t st0 = (uint32_t)__cvta_generic_to_shared(sm);

    const int tid = threadIdx.x;
    const int wid = tid >> 5, lane = tid & 31;
    const int warp_m = wid >> 2, warp_n = wid & 3;
    const int r = lane >> 2, qq = lane & 3;
    const int i0 = blockIdx.x * MT;
    const size_t jbase = (size_t)blockIdx.y * (NROWS / JSPLIT);

    // per-thread load units: 2 for A (u = tid, tid+512), 2 for B
    const int ur0 = tid >> 3, uq0 = tid & 7;
    const int ur1 = (tid + 512) >> 3, uq1 = tid & 7;
    const uint32_t dA0 = ur0 * ROWB + uq0 * 16;
    const uint32_t dA1 = ur1 * ROWB + uq1 * 16;
    const __nv_bfloat16* sA0 = g_xb + (size_t)(i0 + ur0) * DDIM + uq0 * 8;
    const __nv_bfloat16* sA1 = g_xb + (size_t)(i0 + ur1) * DDIM + uq1 * 8;

    // ldmatrix base offsets (per thread)
    const uint32_t aFragOff = (uint32_t)((warp_m * 32 + (lane & 15)) * ROWB + (lane >> 4) * 16);
    const uint32_t bFragOff = (uint32_t)(ASTAGE_B + (warp_n * 32 + (lane & 15)) * ROWB + (lane >> 4) * 16);

    float acc[2][4][4];
    #pragma unroll
    for (int mb = 0; mb < 2; mb++)
        #pragma unroll
        for (int nb = 0; nb < 4; nb++)
            #pragma unroll
            for (int e = 0; e < 4; e++) acc[mb][nb][e] = 0.f;

    float t5[4][5];
    #pragma unroll
    for (int a = 0; a < 4; a++)
        #pragma unroll
        for (int s = 0; s < 5; s++) t5[a][s] = 3.0e38f;

    float sqi[4];
    #pragma unroll
    for (int a = 0; a < 4; a++)
        sqi[a] = __ldg(&g_sq[i0 + warp_m * 32 + (a >> 1) * 16 + (a & 1) * 8 + r]);

    auto issue_load = [&](int it, int slot) {
        const size_t j0 = jbase + (size_t)(it >> 4) * NT;
        const size_t koff = (size_t)(it & (KCHUNKS - 1)) * KT;
        const uint32_t sb = st0 + slot * STAGE_B;
        cp_async16(sb + dA0, sA0 + koff);
        cp_async16(sb + dA1, sA1 + koff);
        const __nv_bfloat16* bp0 = g_xb + (j0 + ur0) * DDIM + uq0 * 8 + koff;
        const __nv_bfloat16* bp1 = g_xb + (j0 + ur1) * DDIM + uq1 * 8 + koff;
        cp_async16(sb + ASTAGE_B + dA0, bp0);
        cp_async16(sb + ASTAGE_B + dA1, bp1);
        asm volatile("cp.async.commit_group;" ::: "memory");
    };

    issue_load(0, 0);
    issue_load(1, 1);

    #pragma unroll 1
    for (int it = 0; it < NITERS; it++) {
        if (it < NITERS - 1) asm volatile("cp.async.wait_group 1;" ::: "memory");
        else                 asm volatile("cp.async.wait_group 0;" ::: "memory");
        __syncthreads();
        if (it + 2 < NITERS) issue_load(it + 2, (it + 2) % NSTAGE);

        const uint32_t sb = st0 + (it % NSTAGE) * STAGE_B;
        const uint32_t aB = sb + aFragOff;
        const uint32_t bB = sb + bFragOff;

        #pragma unroll
        for (int ks = 0; ks < 4; ks++) {
            uint32_t a0[4], a1[4], b0[4], b1[4];
            ldm4(a0, aB + ks * 32);
            ldm4(a1, aB + 16 * ROWB + ks * 32);
            ldm4(b0, bB + ks * 32);
            ldm4(b1, bB + 16 * ROWB + ks * 32);
            mma16816(acc[0][0], a0, b0[0], b0[2]);
            mma16816(acc[1][0], a1, b0[0], b0[2]);
            mma16816(acc[0][1], a0, b0[1], b0[3]);
            mma16816(acc[1][1], a1, b0[1], b0[3]);
            mma16816(acc[0][2], a0, b1[0], b1[2]);
            mma16816(acc[1][2], a1, b1[0], b1[2]);
            mma16816(acc[0][3], a0, b1[1], b1[3]);
            mma16816(acc[1][3], a1, b1[1], b1[3]);
        }

        if ((it & (KCHUNKS - 1)) == (KCHUNKS - 1)) {
            // epilogue for this j-tile
            const size_t j0 = jbase + (size_t)(it >> 4) * NT;
            #pragma unroll
            for (int mb = 0; mb < 2; mb++)
                #pragma unroll
                for (int h = 0; h < 2; h++) {
                    const int a = mb * 2 + h;
                    const int gi = i0 + warp_m * 32 + mb * 16 + h * 8 + r;
                    #pragma unroll
                    for (int nb = 0; nb < 4; nb++)
                        #pragma unroll
                        for (int c = 0; c < 2; c++) {
                            const int cl = warp_n * 32 + nb * 8 + qq * 2 + c;
                            const int gj = (int)j0 + cl;
                            float d2 = sqi[a] + __ldg(&g_sq[gj])
                                       - 2.0f * acc[mb][nb][h * 2 + c];
                            d2 = fmaxf(d2, 0.0f);
                            if (gj != gi) ins5(t5[a], d2);
                            acc[mb][nb][h * 2 + c] = 0.f;
                        }
                }
        }
    }

    // CTA merge: 16 contributors x 5 per row
    __syncthreads();
    float (*cand)[81] = reinterpret_cast<float (*)[81]>(sm);
    const int g = warp_n * 4 + qq;   // 0..15
    #pragma unroll
    for (int a = 0; a < 4; a++) {
        int rl = warp_m * 32 + (a >> 1) * 16 + (a & 1) * 8 + r;
        #pragma unroll
        for (int s = 0; s < 5; s++) cand[rl][g * 5 + s] = t5[a][s];
    }
    __syncthreads();
    if (tid < MT) {
        float t[5] = {3e38f, 3e38f, 3e38f, 3e38f, 3e38f};
        #pragma unroll
        for (int k = 0; k < 80; k++) ins5(t, cand[tid][k]);
        #pragma unroll
        for (int s = 0; s < 5; s++) g_cand[blockIdx.y][i0 + tid][s] = t[s];
    }
}

// ---------------------------------------------------------------------------
// Kernel C: merge splits -> score -> weight -> scale real/imag into out[2,...]
// ---------------------------------------------------------------------------
__global__ __launch_bounds__(256) void finalize_kernel(const float* __restrict__ xr,
                                                       const float* __restrict__ xi,
                                                       float* __restrict__ out) {
    const int row = blockIdx.x;
    const int tid = threadIdx.x;
    __shared__ float wsh;
    if (tid == 0) {
        float t[5] = {3e38f, 3e38f, 3e38f, 3e38f, 3e38f};
        #pragma unroll
        for (int jb = 0; jb < JSPLIT; jb++)
            #pragma unroll
            for (int s = 0; s < 5; s++) ins5(t, g_cand[jb][row][s]);
        float sc = (sqrtf(t[0]) + sqrtf(t[1]) + sqrtf(t[2]) + sqrtf(t[3]) + sqrtf(t[4])) * 0.2f;
        wsh = (sc > 0.1f) ? expf(-sc * (1.0f / 32.0f)) : 0.0f;
    }
    __syncthreads();
    const float w = wsh;
    float4 a = reinterpret_cast<const float4*>(xr + (size_t)row * DDIM)[tid];
    float4 b = reinterpret_cast<const float4*>(xi + (size_t)row * DDIM)[tid];
    a.x *= w; a.y *= w; a.z *= w; a.w *= w;
    b.x *= w; b.y *= w; b.z *= w; b.w *= w;
    reinterpret_cast<float4*>(out + (size_t)row * DDIM)[tid] = a;
    reinterpret_cast<float4*>(out + ((size_t)NROWS + row) * DDIM)[tid] = b;
}

// ---------------------------------------------------------------------------
extern "C" void kernel_launch(void* const* d_in, const int* in_sizes, int n_in,
                              void* d_out, int out_size) {
    const float* xr = (const float*)d_in[0];
    const float* xi = (const float*)d_in[1];
    float* out = (float*)d_out;

    cudaFuncSetAttribute(gram_kernel, cudaFuncAttributeMaxDynamicSharedMemorySize, SMEM_DYN);

    prep_kernel<<<NROWS, 256>>>(xr);
    dim3 gridB(NROWS / MT, JSPLIT);
    gram_kernel<<<gridB, 512, SMEM_DYN>>>();
    finalize_kernel<<<NROWS, 256>>>(xr, xi, out);
}

// round 6
// speedup vs baseline: 1.4244x; 1.1594x over previous
#include <cuda_runtime.h>
#include <cuda_bf16.h>
#include <cstdint>

#define NROWS 8192
#define DDIM  1024

#define MT 128
#define NT 128
#define KT 64                       // bf16 per K chunk
#define STR 72                      // smem row stride in bf16 elems (144B; conflict-free ldmatrix)
#define ROWB (STR * 2)              // 144 bytes
#define NSTAGE 3
#define KCHUNKS (DDIM / KT)         // 16
#define NBLK (NROWS / MT)           // 64
#define NTILES (NBLK * (NBLK + 1) / 2)   // 2080 upper-triangle tiles

#define ASTAGE_B (MT * ROWB)              // 18432
#define STAGE_B  (2 * ASTAGE_B)           // 36864
#define SMEM_DYN (NSTAGE * STAGE_B)       // 110592
// epilogue aliases: colc 128x133 f32 = 68096 B, rowc 128x81 f32 = 41472 B (sum 109568 <= 110592)
#define COLC_W 133
#define ROWC_OFF 68096

__device__ __align__(16) __nv_bfloat16 g_xb[(size_t)NROWS * DDIM];
__device__ float g_sq[NROWS];
__device__ float g_cand[NBLK][NROWS][5];   // slot = "other" block index; all 64 written per row

__device__ __forceinline__ void ins5(float t[5], float v) {
    if (v < t[4]) {
        t[4] = v;
        if (t[4] < t[3]) { float x = t[3]; t[3] = t[4]; t[4] = x;
        if (t[3] < t[2]) { float x = t[2]; t[2] = t[3]; t[3] = x;
        if (t[2] < t[1]) { float x = t[1]; t[1] = t[2]; t[2] = x;
        if (t[1] < t[0]) { float x = t[0]; t[0] = t[1]; t[1] = x; } } } }
    }
}

__device__ __forceinline__ void cp_async16(uint32_t dst, const void* src) {
    asm volatile("cp.async.cg.shared.global [%0], [%1], 16;" :: "r"(dst), "l"(src));
}
__device__ __forceinline__ void ldm4(uint32_t r[4], uint32_t addr) {
    asm volatile("ldmatrix.sync.aligned.m8n8.x4.shared.b16 {%0,%1,%2,%3}, [%4];"
                 : "=r"(r[0]), "=r"(r[1]), "=r"(r[2]), "=r"(r[3]) : "r"(addr));
}
__device__ __forceinline__ void mma16816(float c[4], const uint32_t a[4],
                                         uint32_t b0, uint32_t b1) {
    asm volatile(
        "mma.sync.aligned.m16n8k16.row.col.f32.bf16.bf16.f32 "
        "{%0,%1,%2,%3}, {%4,%5,%6,%7}, {%8,%9}, {%0,%1,%2,%3};\n"
        : "+f"(c[0]), "+f"(c[1]), "+f"(c[2]), "+f"(c[3])
        : "r"(a[0]), "r"(a[1]), "r"(a[2]), "r"(a[3]), "r"(b0), "r"(b1));
}

// ---------------------------------------------------------------------------
// Kernel A: bf16 convert + squared norms
// ---------------------------------------------------------------------------
__global__ __launch_bounds__(256) void prep_kernel(const float* __restrict__ xr) {
    int row = blockIdx.x;
    int tid = threadIdx.x;
    float4 v = reinterpret_cast<const float4*>(xr + (size_t)row * DDIM)[tid];
    __nv_bfloat162 h0 = __floats2bfloat162_rn(v.x, v.y);
    __nv_bfloat162 h1 = __floats2bfloat162_rn(v.z, v.w);
    uint2 pk;
    pk.x = *reinterpret_cast<uint32_t*>(&h0);
    pk.y = *reinterpret_cast<uint32_t*>(&h1);
    reinterpret_cast<uint2*>(g_xb + (size_t)row * DDIM)[tid] = pk;

    float s = v.x * v.x + v.y * v.y + v.z * v.z + v.w * v.w;
    #pragma unroll
    for (int o = 16; o; o >>= 1) s += __shfl_xor_sync(0xffffffffu, s, o);
    __shared__ float red[8];
    if ((tid & 31) == 0) red[tid >> 5] = s;
    __syncthreads();
    if (tid == 0) {
        float tot = 0.f;
        #pragma unroll
        for (int i = 0; i < 8; i++) tot += red[i];
        g_sq[row] = tot;
    }
}

// ---------------------------------------------------------------------------
// Kernel B: symmetric Gram — one upper-triangle 128x128 tile per CTA.
// Row top-5 -> g_cand[bj][i0+row]; column top-5 -> g_cand[bi][j0+col] (off-diag).
// ---------------------------------------------------------------------------
__global__ __launch_bounds__(512, 1) void gram_kernel() {
    extern __shared__ __align__(16) unsigned char sm[];
    const uint32_t st0 = (uint32_t)__cvta_generic_to_shared(sm);

    // decode upper-triangle tile (bi, bj), bj >= bi
    int trem = blockIdx.x, bi = 0;
    while (trem >= NBLK - bi) { trem -= NBLK - bi; bi++; }
    const int bj = bi + trem;
    const int i0 = bi * MT;
    const int j0 = bj * NT;

    const int tid = threadIdx.x;
    const int wid = tid >> 5, lane = tid & 31;
    const int warp_m = wid >> 2, warp_n = wid & 3;
    const int r = lane >> 2, qq = lane & 3;

    // per-thread load units: 2 for A, 2 for B
    const int ur0 = tid >> 3, uq0 = tid & 7;
    const int ur1 = (tid + 512) >> 3;
    const uint32_t dA0 = ur0 * ROWB + uq0 * 16;
    const uint32_t dA1 = ur1 * ROWB + uq0 * 16;
    const __nv_bfloat16* aP0 = g_xb + (size_t)(i0 + ur0) * DDIM + uq0 * 8;
    const __nv_bfloat16* aP1 = g_xb + (size_t)(i0 + ur1) * DDIM + uq0 * 8;
    const __nv_bfloat16* bP0 = g_xb + (size_t)(j0 + ur0) * DDIM + uq0 * 8;
    const __nv_bfloat16* bP1 = g_xb + (size_t)(j0 + ur1) * DDIM + uq0 * 8;

    const uint32_t aFragOff = (uint32_t)((warp_m * 32 + (lane & 15)) * ROWB + (lane >> 4) * 16);
    const uint32_t bFragOff = (uint32_t)(ASTAGE_B + (warp_n * 32 + (lane & 15)) * ROWB + (lane >> 4) * 16);

    float acc[2][4][4];
    #pragma unroll
    for (int mb = 0; mb < 2; mb++)
        #pragma unroll
        for (int nb = 0; nb < 4; nb++)
            #pragma unroll
            for (int e = 0; e < 4; e++) acc[mb][nb][e] = 0.f;

    auto issue_load = [&](int it, int slot) {
        const size_t koff = (size_t)it * KT;
        const uint32_t sb = st0 + slot * STAGE_B;
        cp_async16(sb + dA0, aP0 + koff);
        cp_async16(sb + dA1, aP1 + koff);
        cp_async16(sb + ASTAGE_B + dA0, bP0 + koff);
        cp_async16(sb + ASTAGE_B + dA1, bP1 + koff);
        asm volatile("cp.async.commit_group;" ::: "memory");
    };

    issue_load(0, 0);
    issue_load(1, 1);

    #pragma unroll 1
    for (int it = 0; it < KCHUNKS; it++) {
        if (it < KCHUNKS - 1) asm volatile("cp.async.wait_group 1;" ::: "memory");
        else                  asm volatile("cp.async.wait_group 0;" ::: "memory");
        __syncthreads();
        if (it + 2 < KCHUNKS) issue_load(it + 2, (it + 2) % NSTAGE);

        const uint32_t sb = st0 + (it % NSTAGE) * STAGE_B;
        const uint32_t aB = sb + aFragOff;
        const uint32_t bB = sb + bFragOff;

        #pragma unroll
        for (int ks = 0; ks < 4; ks++) {
            uint32_t a0[4], a1[4], b0[4], b1[4];
            ldm4(a0, aB + ks * 32);
            ldm4(a1, aB + 16 * ROWB + ks * 32);
            ldm4(b0, bB + ks * 32);
            ldm4(b1, bB + 16 * ROWB + ks * 32);
            mma16816(acc[0][0], a0, b0[0], b0[2]);
            mma16816(acc[1][0], a1, b0[0], b0[2]);
            mma16816(acc[0][1], a0, b0[1], b0[3]);
            mma16816(acc[1][1], a1, b0[1], b0[3]);
            mma16816(acc[0][2], a0, b1[0], b1[2]);
            mma16816(acc[1][2], a1, b1[0], b1[2]);
            mma16816(acc[0][3], a0, b1[1], b1[3]);
            mma16816(acc[1][3], a1, b1[1], b1[3]);
        }
    }

    __syncthreads();   // pipeline smem dead -> alias epilogue buffers

    float (*colc)[COLC_W] = reinterpret_cast<float (*)[COLC_W]>(sm);
    float (*rowc)[81]     = reinterpret_cast<float (*)[81]>(sm + ROWC_OFF);
    const int cid = warp_m * 8 + r;

    float t5[4][5];
    #pragma unroll
    for (int a = 0; a < 4; a++)
        #pragma unroll
        for (int s = 0; s < 5; s++) t5[a][s] = 3.0e38f;

    #pragma unroll
    for (int mb = 0; mb < 2; mb++)
        #pragma unroll
        for (int h = 0; h < 2; h++) {
            const int a = mb * 2 + h;
            const int gi = i0 + warp_m * 32 + mb * 16 + h * 8 + r;
            const float sqi = __ldg(&g_sq[gi]);
            #pragma unroll
            for (int nb = 0; nb < 4; nb++)
                #pragma unroll
                for (int c = 0; c < 2; c++) {
                    const int cl = warp_n * 32 + nb * 8 + qq * 2 + c;
                    const int gj = j0 + cl;
                    float d2 = sqi + __ldg(&g_sq[gj]) - 2.0f * acc[mb][nb][h * 2 + c];
                    d2 = fmaxf(d2, 0.0f);
                    if (gj != gi) ins5(t5[a], d2); else d2 = 3.0e38f;
                    colc[cl][cid * 4 + a] = d2;
                }
        }

    // row candidates: 16 contributors (warp_n x qq) x 5 per row
    const int g = warp_n * 4 + qq;
    #pragma unroll
    for (int a = 0; a < 4; a++) {
        int rl = warp_m * 32 + (a >> 1) * 16 + (a & 1) * 8 + r;
        #pragma unroll
        for (int s = 0; s < 5; s++) rowc[rl][g * 5 + s] = t5[a][s];
    }
    __syncthreads();

    if (tid < MT) {
        float t[5] = {3e38f, 3e38f, 3e38f, 3e38f, 3e38f};
        #pragma unroll
        for (int k = 0; k < 80; k++) ins5(t, rowc[tid][k]);
        #pragma unroll
        for (int s = 0; s < 5; s++) g_cand[bj][i0 + tid][s] = t[s];
    } else if (tid < 256 && bi != bj) {
        const int cl = tid - 128;
        float t[5] = {3e38f, 3e38f, 3e38f, 3e38f, 3e38f};
        #pragma unroll
        for (int k = 0; k < 128; k++) ins5(t, colc[cl][k]);
        #pragma unroll
        for (int s = 0; s < 5; s++) g_cand[bi][j0 + cl][s] = t[s];
    }
}

// ---------------------------------------------------------------------------
// Kernel C: merge 64 candidate slots -> score -> weight -> scale into out[2,...]
// ---------------------------------------------------------------------------
__global__ __launch_bounds__(256) void finalize_kernel(const float* __restrict__ xr,
                                                       const float* __restrict__ xi,
                                                       float* __restrict__ out) {
    const int row = blockIdx.x;
    const int tid = threadIdx.x;
    __shared__ float buf[40];
    __shared__ float wsh;
    if (tid < 8) {
        float t[5] = {3e38f, 3e38f, 3e38f, 3e38f, 3e38f};
        #pragma unroll
        for (int s8 = 0; s8 < 8; s8++) {
            const int slot = tid * 8 + s8;
            #pragma unroll
            for (int s = 0; s < 5; s++) ins5(t, g_cand[slot][row][s]);
        }
        #pragma unroll
        for (int s = 0; s < 5; s++) buf[tid * 5 + s] = t[s];
    }
    __syncthreads();
    if (tid == 0) {
        float t[5] = {3e38f, 3e38f, 3e38f, 3e38f, 3e38f};
        #pragma unroll
        for (int k = 0; k < 40; k++) ins5(t, buf[k]);
        float sc = (sqrtf(t[0]) + sqrtf(t[1]) + sqrtf(t[2]) + sqrtf(t[3]) + sqrtf(t[4])) * 0.2f;
        wsh = (sc > 0.1f) ? expf(-sc * (1.0f / 32.0f)) : 0.0f;
    }
    __syncthreads();
    const float w = wsh;
    float4 a = reinterpret_cast<const float4*>(xr + (size_t)row * DDIM)[tid];
    float4 b = reinterpret_cast<const float4*>(xi + (size_t)row * DDIM)[tid];
    a.x *= w; a.y *= w; a.z *= w; a.w *= w;
    b.x *= w; b.y *= w; b.z *= w; b.w *= w;
    reinterpret_cast<float4*>(out + (size_t)row * DDIM)[tid] = a;
    reinterpret_cast<float4*>(out + ((size_t)NROWS + row) * DDIM)[tid] = b;
}

// ---------------------------------------------------------------------------
extern "C" void kernel_launch(void* const* d_in, const int* in_sizes, int n_in,
                              void* d_out, int out_size) {
    const float* xr = (const float*)d_in[0];
    const float* xi = (const float*)d_in[1];
    float* out = (float*)d_out;

    cudaFuncSetAttribute(gram_kernel, cudaFuncAttributeMaxDynamicSharedMemorySize, SMEM_DYN);

    prep_kernel<<<NROWS, 256>>>(xr);
    gram_kernel<<<NTILES, 512, SMEM_DYN>>>();
    finalize_kernel<<<NROWS, 256>>>(xr, xi, out);
}